// round 2
// baseline (speedup 1.0000x reference)
#include <cuda_runtime.h>
#include <math.h>

#define T_STEPS 512
#define BATCH   128
#define IN_DIM  544
#define HID     512
#define G4H     2048
#define NACT    19      // 18 logits + 1 value
#define NBLK    128     // persistent grid (co-resident on 148 SMs)
#define NTHR    256

// ---------------- scratch (device globals; no runtime allocation) ------------
__device__ float g_pre0[(size_t)T_STEPS * BATCH * G4H];     // 512 MB: x@W_ih0^T + biases
__device__ float g_hidden[(size_t)T_STEPS * BATCH * HID];   // 128 MB: layer-1 h per step
__device__ float g_h0[2][BATCH][HID];                       // ping-pong layer0 h
__device__ float g_h1[2][BATCH][HID];                       // ping-pong layer1 h
__device__ unsigned int g_bar_count;
__device__ unsigned int g_bar_release;

// ---------------- init: reset barrier + seed h state -------------------------
__global__ void init_kernel(const float* __restrict__ h0) {
    if (blockIdx.x == 0 && threadIdx.x == 0) { g_bar_count = 0u; g_bar_release = 0u; }
    const int n = BATCH * HID;
    for (int i = blockIdx.x * blockDim.x + threadIdx.x; i < n; i += gridDim.x * blockDim.x) {
        (&g_h0[0][0][0])[i] = h0[i];        // layer 0
        (&g_h1[0][0][0])[i] = h0[n + i];    // layer 1
    }
}

// ---------------- precompute GEMM: pre0[m,n] = sum_k X[m,k]*W[n,k] + b -------
__global__ void __launch_bounds__(256)
pre_gemm_kernel(const float* __restrict__ X, const float* __restrict__ W,
                const float* __restrict__ bA, const float* __restrict__ bB)
{
    __shared__ float Xs[16][68];
    __shared__ float Ws[16][68];
    const int tid = threadIdx.x;
    const int bn  = blockIdx.x * 64;
    const int bm  = blockIdx.y * 64;
    const int tx  = tid & 15;
    const int ty  = tid >> 4;
    const int lm  = tid >> 2;
    const int lk  = (tid & 3) << 2;

    float acc[4][4];
#pragma unroll
    for (int i = 0; i < 4; i++)
#pragma unroll
        for (int j = 0; j < 4; j++) acc[i][j] = 0.f;

    for (int k0 = 0; k0 < IN_DIM; k0 += 16) {
        float4 xa = *(const float4*)&X[(size_t)(bm + lm) * IN_DIM + k0 + lk];
        float4 wa = *(const float4*)&W[(size_t)(bn + lm) * IN_DIM + k0 + lk];
        __syncthreads();
        Xs[lk + 0][lm] = xa.x; Xs[lk + 1][lm] = xa.y; Xs[lk + 2][lm] = xa.z; Xs[lk + 3][lm] = xa.w;
        Ws[lk + 0][lm] = wa.x; Ws[lk + 1][lm] = wa.y; Ws[lk + 2][lm] = wa.z; Ws[lk + 3][lm] = wa.w;
        __syncthreads();
#pragma unroll
        for (int k = 0; k < 16; k++) {
            float4 av = *(const float4*)&Xs[k][ty << 2];
            float4 bv = *(const float4*)&Ws[k][tx << 2];
            float a4[4] = {av.x, av.y, av.z, av.w};
            float b4[4] = {bv.x, bv.y, bv.z, bv.w};
#pragma unroll
            for (int i = 0; i < 4; i++)
#pragma unroll
                for (int j = 0; j < 4; j++) acc[i][j] = fmaf(a4[i], b4[j], acc[i][j]);
        }
    }
    float bb[4];
#pragma unroll
    for (int j = 0; j < 4; j++) { int n = bn + (tx << 2) + j; bb[j] = bA[n] + bB[n]; }
#pragma unroll
    for (int i = 0; i < 4; i++) {
        size_t m = (size_t)bm + (ty << 2) + i;
        float4 v = make_float4(acc[i][0] + bb[0], acc[i][1] + bb[1],
                               acc[i][2] + bb[2], acc[i][3] + bb[3]);
        *(float4*)&g_pre0[m * G4H + bn + (tx << 2)] = v;
    }
}

// ---------------- persistent LSTM kernel -------------------------------------
__device__ __forceinline__ float sigmoidf_(float x) { return 1.f / (1.f + expf(-x)); }

__device__ __forceinline__ void grid_bar(unsigned int phase) {
    __threadfence();
    __syncthreads();
    if (threadIdx.x == 0) {
        unsigned int arrived = atomicAdd(&g_bar_count, 1u) + 1u;
        if (arrived == (unsigned)NBLK * phase) {
            atomicExch(&g_bar_release, phase);
        } else {
            while (atomicAdd(&g_bar_release, 0u) < phase) { __nanosleep(32); }
        }
    }
    __syncthreads();
}

// acc[g*2+j] += sum_k h[b,k] * W[g*4 + 2*up + j, k]   (Wt pre-offset by 2*up rows)
template <bool USE_MASK>
__device__ __forceinline__ void accum_K(float* __restrict__ acc,
                                        const float* __restrict__ hsrc,
                                        const float* __restrict__ Wt,
                                        const float* __restrict__ msm,
                                        float* __restrict__ hbuf,
                                        int b, int lk, int lb0)
{
    for (int kc = 0; kc < 4; kc++) {
        const int k0 = kc << 7;
        __syncthreads();
#pragma unroll 8
        for (int bb = 0; bb < 64; bb++) {
            const int bl = lb0 + bb;
            float v = __ldcg(&hsrc[bl * HID + k0 + lk]);   // L2 (skip stale L1)
            if (USE_MASK) v *= msm[bl];
            hbuf[lk * 129 + bl] = v;                        // conflict-free [k][b]+pad
        }
        __syncthreads();
#pragma unroll 4
        for (int k = 0; k < 128; k += 4) {
            const float h0v = hbuf[(k + 0) * 129 + b];
            const float h1v = hbuf[(k + 1) * 129 + b];
            const float h2v = hbuf[(k + 2) * 129 + b];
            const float h3v = hbuf[(k + 3) * 129 + b];
#pragma unroll
            for (int g = 0; g < 4; g++) {
#pragma unroll
                for (int j = 0; j < 2; j++) {
                    const float4 w = *(const float4*)&Wt[(g << 11) + (j << 9) + k0 + k];
                    float a = acc[(g << 1) + j];
                    a = fmaf(h0v, w.x, a);
                    a = fmaf(h1v, w.y, a);
                    a = fmaf(h2v, w.z, a);
                    a = fmaf(h3v, w.w, a);
                    acc[(g << 1) + j] = a;
                }
            }
        }
    }
}

__global__ void __launch_bounds__(NTHR, 1)
lstm_kernel(const int* __restrict__ done,
            const float* __restrict__ c0_in,
            const float* __restrict__ W_hh0,
            const float* __restrict__ W_ih1,
            const float* __restrict__ W_hh1,
            const float* __restrict__ b_ih1,
            const float* __restrict__ b_hh1,
            float* __restrict__ out_hT,
            float* __restrict__ out_cT)
{
    extern __shared__ float smem[];
    float* W0s  = smem;                    // 16*512 : W_hh0 rows for this block's units
    float* W1i  = W0s + 16 * HID;          // 16*512 : W_ih1 rows
    float* W1h  = W1i + 16 * HID;          // 16*512 : W_hh1 rows
    float* hbuf = W1h + 16 * HID;          // 128*129 staging
    float* msm  = hbuf + 128 * 129;        // 128 done-masks

    const int tid = threadIdx.x;
    const int bid = blockIdx.x;
    const int b   = tid & 127;             // batch element this thread owns
    const int up  = tid >> 7;              // unit pair select (0/1)
    const int lk  = tid & 127;             // loader: k index
    const int lb0 = (tid >> 7) << 6;       // loader: batch base
    const int u0  = bid * 4;               // first hidden unit of this block

    // resident weights: rows r = gate*4 + lu  ->  global row gate*HID + u0 + lu
    for (int i = tid; i < 16 * (HID / 4); i += NTHR) {
        int r = i >> 7, c4 = i & 127;
        int g = r >> 2, lu = r & 3;
        size_t grow = (size_t)g * HID + u0 + lu;
        ((float4*)W0s)[i] = ((const float4*)W_hh0)[grow * (HID / 4) + c4];
        ((float4*)W1i)[i] = ((const float4*)W_ih1)[grow * (HID / 4) + c4];
        ((float4*)W1h)[i] = ((const float4*)W_hh1)[grow * (HID / 4) + c4];
    }

    float bias1[8];
#pragma unroll
    for (int g = 0; g < 4; g++)
#pragma unroll
        for (int j = 0; j < 2; j++) {
            int row = g * HID + u0 + 2 * up + j;
            bias1[g * 2 + j] = b_ih1[row] + b_hh1[row];
        }

    float c0r[2], c1r[2];
#pragma unroll
    for (int j = 0; j < 2; j++) {
        int u = u0 + 2 * up + j;
        c0r[j] = c0_in[(0 * BATCH + b) * HID + u];
        c1r[j] = c0_in[(1 * BATCH + b) * HID + u];
    }

    const float* Wt0  = W0s + (2 * up) * HID;
    const float* Wt1i = W1i + (2 * up) * HID;
    const float* Wt1h = W1h + (2 * up) * HID;

    unsigned int phase = 0;

    for (int t = 0; t < T_STEPS; t++) {
        const int p = t & 1;
        if (tid < BATCH) msm[tid] = 1.0f - (float)done[t * BATCH + tid];
        const float mk = 1.0f - (float)done[t * BATCH + b];

        // ---- layer 0 : gates = pre0[t] + (h0*mask) @ W_hh0^T ----
        float acc[8];
#pragma unroll
        for (int i = 0; i < 8; i++) acc[i] = 0.f;
        accum_K<true>(acc, &g_h0[p][0][0], Wt0, msm, hbuf, b, lk, lb0);

        const size_t pbase = ((size_t)t * BATCH + b) * G4H + u0 + 2 * up;
#pragma unroll
        for (int g = 0; g < 4; g++)
#pragma unroll
            for (int j = 0; j < 2; j++)
                acc[g * 2 + j] += g_pre0[pbase + (size_t)g * HID + j];

#pragma unroll
        for (int j = 0; j < 2; j++) {
            float ig = sigmoidf_(acc[0 + j]);
            float fg = sigmoidf_(acc[2 + j]);
            float gg = tanhf(acc[4 + j]);
            float og = sigmoidf_(acc[6 + j]);
            float c  = fmaf(fg, c0r[j] * mk, ig * gg);
            c0r[j]   = c;
            g_h0[p ^ 1][b][u0 + 2 * up + j] = og * tanhf(c);
        }

        grid_bar(++phase);

        // ---- layer 1 : gates = b1 + h0_new @ W_ih1^T + (h1*mask) @ W_hh1^T ----
#pragma unroll
        for (int i = 0; i < 8; i++) acc[i] = bias1[i];
        accum_K<false>(acc, &g_h0[p ^ 1][0][0], Wt1i, msm, hbuf, b, lk, lb0);
        accum_K<true >(acc, &g_h1[p][0][0],     Wt1h, msm, hbuf, b, lk, lb0);

#pragma unroll
        for (int j = 0; j < 2; j++) {
            float ig = sigmoidf_(acc[0 + j]);
            float fg = sigmoidf_(acc[2 + j]);
            float gg = tanhf(acc[4 + j]);
            float og = sigmoidf_(acc[6 + j]);
            float c  = fmaf(fg, c1r[j] * mk, ig * gg);
            c1r[j]   = c;
            float h  = og * tanhf(c);
            int u = u0 + 2 * up + j;
            g_h1[p ^ 1][b][u] = h;
            g_hidden[((size_t)t * BATCH + b) * HID + u] = h;
        }

        grid_bar(++phase);
    }

    // ---- final state out (T even -> final buffers are index 0) ----
#pragma unroll
    for (int j = 0; j < 2; j++) {
        int u = u0 + 2 * up + j;
        out_cT[(0 * BATCH + b) * HID + u] = c0r[j];
        out_cT[(1 * BATCH + b) * HID + u] = c1r[j];
    }
    for (int i = bid * NTHR + tid; i < BATCH * HID; i += NBLK * NTHR) {
        out_hT[i]               = __ldcg(&(&g_h0[0][0][0])[i]);
        out_hT[BATCH * HID + i] = __ldcg(&(&g_h1[0][0][0])[i]);
    }
}

// ---------------- actor/critic heads -----------------------------------------
__global__ void __launch_bounds__(256)
head_kernel(const float* __restrict__ Wa, const float* __restrict__ ba,
            const float* __restrict__ Wc, const float* __restrict__ bc,
            float* __restrict__ out)
{
    __shared__ float Ws[NACT * HID];
    __shared__ float bs[NACT];
    for (int i = threadIdx.x; i < 18 * HID; i += blockDim.x) Ws[i] = Wa[i];
    for (int i = threadIdx.x; i < HID; i += blockDim.x) Ws[18 * HID + i] = Wc[i];
    if (threadIdx.x < 18) bs[threadIdx.x] = ba[threadIdx.x];
    if (threadIdx.x == 18) bs[18] = bc[0];
    __syncthreads();

    const int warp = threadIdx.x >> 5;
    const int lane = threadIdx.x & 31;
    const size_t m = (size_t)blockIdx.x * 8 + warp;

    const float* hrow = &g_hidden[m * HID];
    float hv[16];
#pragma unroll
    for (int j = 0; j < 16; j++) hv[j] = hrow[lane + j * 32];

#pragma unroll
    for (int a = 0; a < NACT; a++) {
        float s = 0.f;
#pragma unroll
        for (int j = 0; j < 16; j++) s = fmaf(hv[j], Ws[a * HID + lane + j * 32], s);
#pragma unroll
        for (int off = 16; off > 0; off >>= 1) s += __shfl_xor_sync(0xffffffffu, s, off);
        if (lane == a) out[m * NACT + a] = s + bs[a];
    }
}

// ---------------- launch ------------------------------------------------------
extern "C" void kernel_launch(void* const* d_in, const int* in_sizes, int n_in,
                              void* d_out, int out_size)
{
    (void)in_sizes; (void)n_in; (void)out_size;
    const float* x     = (const float*)d_in[0];
    const int*   done  = (const int*)  d_in[1];
    const float* h0    = (const float*)d_in[2];
    const float* c0    = (const float*)d_in[3];
    const float* W_ih0 = (const float*)d_in[4];
    const float* W_hh0 = (const float*)d_in[5];
    const float* b_ih0 = (const float*)d_in[6];
    const float* b_hh0 = (const float*)d_in[7];
    const float* W_ih1 = (const float*)d_in[8];
    const float* W_hh1 = (const float*)d_in[9];
    const float* b_ih1 = (const float*)d_in[10];
    const float* b_hh1 = (const float*)d_in[11];
    const float* W_a   = (const float*)d_in[12];
    const float* b_a   = (const float*)d_in[13];
    const float* W_c   = (const float*)d_in[14];
    const float* b_c   = (const float*)d_in[15];

    float* out    = (float*)d_out;
    float* out_hT = out + (size_t)T_STEPS * BATCH * NACT;
    float* out_cT = out_hT + 2 * BATCH * HID;

    const int smem_bytes = (3 * 16 * HID + 128 * 129 + 128) * (int)sizeof(float); // 164,864 B
    cudaFuncSetAttribute(lstm_kernel, cudaFuncAttributeMaxDynamicSharedMemorySize, smem_bytes);

    init_kernel<<<64, 256>>>(h0);

    dim3 gg(G4H / 64, (T_STEPS * BATCH) / 64);
    pre_gemm_kernel<<<gg, 256>>>(x, W_ih0, b_ih0, b_hh0);

    lstm_kernel<<<NBLK, NTHR, smem_bytes>>>(done, c0, W_hh0, W_ih1, W_hh1,
                                            b_ih1, b_hh1, out_hT, out_cT);

    head_kernel<<<(T_STEPS * BATCH) / 8, 256>>>(W_a, b_a, W_c, b_c, out);
}

// round 4
// speedup vs baseline: 1.1960x; 1.1960x over previous
#include <cuda_runtime.h>
#include <math.h>

#define T_STEPS 512
#define BATCH   128
#define IN_DIM  544
#define HID     512
#define G4H     2048
#define NACT    19
#define NBLK    128
#define NTHR    128     // lstm kernel threads: 4 warps = 4 units, lane = batch base

// ---------------- scratch ----------------------------------------------------
__device__ float g_pre0[(size_t)T_STEPS * G4H * BATCH];     // [t][n][b] transposed
__device__ float g_hidden[(size_t)T_STEPS * BATCH * HID];
__device__ float g_h0[2][BATCH][HID];
__device__ float g_h1[2][BATCH][HID];
__device__ unsigned int g_bar_count;
__device__ unsigned int g_bar_release;

// ---------------- f32x2 helpers ----------------------------------------------
__device__ __forceinline__ void ffma2(unsigned long long& d, unsigned long long a,
                                      unsigned long long b) {
    asm("fma.rn.f32x2 %0, %1, %2, %0;" : "+l"(d) : "l"(a), "l"(b));
}
__device__ __forceinline__ unsigned long long dupf(float a) {
    unsigned long long r; asm("mov.b64 %0, {%1, %1};" : "=l"(r) : "f"(a)); return r;
}
__device__ __forceinline__ float2 unpk(unsigned long long v) {
    float2 r; asm("mov.b64 {%0, %1}, %2;" : "=f"(r.x), "=f"(r.y) : "l"(v)); return r;
}

// ---------------- init -------------------------------------------------------
__global__ void init_kernel(const float* __restrict__ h0) {
    if (blockIdx.x == 0 && threadIdx.x == 0) { g_bar_count = 0u; g_bar_release = 0u; }
    const int n = BATCH * HID;
    for (int i = blockIdx.x * blockDim.x + threadIdx.x; i < n; i += gridDim.x * blockDim.x) {
        (&g_h0[0][0][0])[i] = h0[i];
        (&g_h1[0][0][0])[i] = h0[n + i];
    }
}

// ---------------- precompute GEMM (f32x2) ------------------------------------
// g_pre0[t][n][b] = sum_k X[t*128+b, k] * W_ih0[n, k] + b_ih0[n] + b_hh0[n]
__global__ void __launch_bounds__(256)
pre_gemm_kernel(const float* __restrict__ X, const float* __restrict__ W,
                const float* __restrict__ bA, const float* __restrict__ bB)
{
    __shared__ float Xs[16][68];
    __shared__ float Ws[16][68];
    __shared__ float Ts[64 * 68];
    const int tid = threadIdx.x;
    const int bn  = blockIdx.x * 64;
    const int bm  = blockIdx.y * 64;
    const int tx  = tid & 15;
    const int ty  = tid >> 4;
    const int lm  = tid >> 2;
    const int lk  = (tid & 3) << 2;

    unsigned long long acc2[4][2];
#pragma unroll
    for (int i = 0; i < 4; i++) { acc2[i][0] = 0ull; acc2[i][1] = 0ull; }

    for (int k0 = 0; k0 < IN_DIM; k0 += 16) {
        float4 xa = *(const float4*)&X[(size_t)(bm + lm) * IN_DIM + k0 + lk];
        float4 wa = *(const float4*)&W[(size_t)(bn + lm) * IN_DIM + k0 + lk];
        __syncthreads();
        Xs[lk + 0][lm] = xa.x; Xs[lk + 1][lm] = xa.y; Xs[lk + 2][lm] = xa.z; Xs[lk + 3][lm] = xa.w;
        Ws[lk + 0][lm] = wa.x; Ws[lk + 1][lm] = wa.y; Ws[lk + 2][lm] = wa.z; Ws[lk + 3][lm] = wa.w;
        __syncthreads();
#pragma unroll
        for (int k = 0; k < 16; k++) {
            float4 av = *(const float4*)&Xs[k][ty << 2];
            ulonglong2 bv = *(const ulonglong2*)&Ws[k][tx << 2];
            unsigned long long a0 = dupf(av.x), a1 = dupf(av.y), a2 = dupf(av.z), a3 = dupf(av.w);
            ffma2(acc2[0][0], a0, bv.x); ffma2(acc2[0][1], a0, bv.y);
            ffma2(acc2[1][0], a1, bv.x); ffma2(acc2[1][1], a1, bv.y);
            ffma2(acc2[2][0], a2, bv.x); ffma2(acc2[2][1], a2, bv.y);
            ffma2(acc2[3][0], a3, bv.x); ffma2(acc2[3][1], a3, bv.y);
        }
    }

    float bb[4];
#pragma unroll
    for (int j = 0; j < 4; j++) { int n = bn + (tx << 2) + j; bb[j] = bA[n] + bB[n]; }

    __syncthreads();
#pragma unroll
    for (int i = 0; i < 4; i++) {
        float2 v01 = unpk(acc2[i][0]);
        float2 v23 = unpk(acc2[i][1]);
        int ml = (ty << 2) + i;
        Ts[((tx << 2) + 0) * 68 + ml] = v01.x + bb[0];
        Ts[((tx << 2) + 1) * 68 + ml] = v01.y + bb[1];
        Ts[((tx << 2) + 2) * 68 + ml] = v23.x + bb[2];
        Ts[((tx << 2) + 3) * 68 + ml] = v23.y + bb[3];
    }
    __syncthreads();

    const int tt = bm >> 7;            // time index
    const int b0 = bm & 127;           // batch base (0 or 64)
    const int nl = tid >> 2;
    const int mq = (tid & 3) << 4;
    float* dst = &g_pre0[((size_t)tt * G4H + bn + nl) * BATCH + b0 + mq];
    const float* src = &Ts[nl * 68 + mq];
#pragma unroll
    for (int s = 0; s < 4; s++)
        ((float4*)dst)[s] = ((const float4*)src)[s];
}

// ---------------- persistent LSTM --------------------------------------------
__device__ __forceinline__ float sigmoidf_(float x) { return 1.f / (1.f + expf(-x)); }

__device__ __forceinline__ void grid_bar(unsigned int phase) {
    __threadfence();
    __syncthreads();
    if (threadIdx.x == 0) {
        unsigned int arrived = atomicAdd(&g_bar_count, 1u) + 1u;
        if (arrived == (unsigned)NBLK * phase) {
            atomicExch(&g_bar_release, phase);
        } else {
            while (*(volatile unsigned int*)&g_bar_release < phase) { __nanosleep(64); }
        }
    }
    __syncthreads();
}

// acc2[g*4+i] (packed over k) += sum_k h[b_i, k] * W[g-th gate row of unit]
template <bool USE_MASK>
__device__ __forceinline__ void accum_K(unsigned long long* __restrict__ acc2,
                                        const float* __restrict__ hsrc,
                                        const float* __restrict__ Wu,
                                        const float* __restrict__ msm,
                                        float* __restrict__ hbuf,
                                        const int tid)
{
    const int lane = tid & 31;
    for (int kc = 0; kc < 4; kc++) {
        const int k0 = kc << 7;
        __syncthreads();
#pragma unroll 4
        for (int it = 0; it < 32; it++) {
            const int idx = (it << 7) + tid;
            const int bl  = idx >> 5;
            const int kq  = (idx & 31) << 2;
            float4 v = __ldcg((const float4*)&hsrc[bl * HID + k0 + kq]);
            if (USE_MASK) { float m = msm[bl]; v.x *= m; v.y *= m; v.z *= m; v.w *= m; }
            *(float4*)&hbuf[bl * 132 + kq] = v;
        }
        __syncthreads();
        const float* hb0 = &hbuf[(lane +  0) * 132];
        const float* hb1 = &hbuf[(lane + 32) * 132];
        const float* hb2 = &hbuf[(lane + 64) * 132];
        const float* hb3 = &hbuf[(lane + 96) * 132];
#pragma unroll 2
        for (int k = 0; k < 128; k += 8) {
            ulonglong2 h0a = *(const ulonglong2*)(hb0 + k);
            ulonglong2 h0b = *(const ulonglong2*)(hb0 + k + 4);
            ulonglong2 h1a = *(const ulonglong2*)(hb1 + k);
            ulonglong2 h1b = *(const ulonglong2*)(hb1 + k + 4);
            ulonglong2 h2a = *(const ulonglong2*)(hb2 + k);
            ulonglong2 h2b = *(const ulonglong2*)(hb2 + k + 4);
            ulonglong2 h3a = *(const ulonglong2*)(hb3 + k);
            ulonglong2 h3b = *(const ulonglong2*)(hb3 + k + 4);
#pragma unroll
            for (int g = 0; g < 4; g++) {
                // FIX (round 4): weight index must include the K-chunk base k0
                ulonglong2 w0 = *(const ulonglong2*)(Wu + (g << 11) + k0 + k);
                ulonglong2 w1 = *(const ulonglong2*)(Wu + (g << 11) + k0 + k + 4);
                unsigned long long* a = &acc2[g << 2];
                ffma2(a[0], h0a.x, w0.x); ffma2(a[0], h0a.y, w0.y);
                ffma2(a[0], h0b.x, w1.x); ffma2(a[0], h0b.y, w1.y);
                ffma2(a[1], h1a.x, w0.x); ffma2(a[1], h1a.y, w0.y);
                ffma2(a[1], h1b.x, w1.x); ffma2(a[1], h1b.y, w1.y);
                ffma2(a[2], h2a.x, w0.x); ffma2(a[2], h2a.y, w0.y);
                ffma2(a[2], h2b.x, w1.x); ffma2(a[2], h2b.y, w1.y);
                ffma2(a[3], h3a.x, w0.x); ffma2(a[3], h3a.y, w0.y);
                ffma2(a[3], h3b.x, w1.x); ffma2(a[3], h3b.y, w1.y);
            }
        }
    }
}

__global__ void __launch_bounds__(NTHR, 1)
lstm_kernel(const int* __restrict__ done,
            const float* __restrict__ c0_in,
            const float* __restrict__ W_hh0,
            const float* __restrict__ W_ih1,
            const float* __restrict__ W_hh1,
            const float* __restrict__ b_ih1,
            const float* __restrict__ b_hh1,
            float* __restrict__ out_hT,
            float* __restrict__ out_cT)
{
    extern __shared__ float smem[];
    float* W0s  = smem;                    // 16 x 512
    float* W1i  = W0s + 16 * HID;
    float* W1h  = W1i + 16 * HID;
    float* hbuf = W1h + 16 * HID;          // 128 x 132
    float* msm  = hbuf + 128 * 132;        // 128 masks

    const int tid  = threadIdx.x;
    const int bid  = blockIdx.x;
    const int lane = tid & 31;
    const int w    = tid >> 5;             // warp = local unit 0..3
    const int u0   = bid * 4;
    const int u    = u0 + w;               // global hidden unit this thread owns

    // load weights: smem row r = g*4+lu  <-  global row g*HID + u0 + lu
    for (int i = tid; i < 16 * (HID / 4); i += NTHR) {
        int r = i >> 7, c4 = i & 127;
        int g = r >> 2, lu = r & 3;
        size_t grow = (size_t)g * HID + u0 + lu;
        ((float4*)W0s)[i] = ((const float4*)W_hh0)[grow * (HID / 4) + c4];
        ((float4*)W1i)[i] = ((const float4*)W_ih1)[grow * (HID / 4) + c4];
        ((float4*)W1h)[i] = ((const float4*)W_hh1)[grow * (HID / 4) + c4];
    }

    float bias1[4];
#pragma unroll
    for (int g = 0; g < 4; g++) bias1[g] = b_ih1[g * HID + u] + b_hh1[g * HID + u];

    float c0r[4], c1r[4];
#pragma unroll
    for (int i = 0; i < 4; i++) {
        int b = lane + (i << 5);
        c0r[i] = c0_in[(0 * BATCH + b) * HID + u];
        c1r[i] = c0_in[(1 * BATCH + b) * HID + u];
    }

    const float* Wu0  = W0s + w * HID;     // gate g row at + g*2048
    const float* Wu1i = W1i + w * HID;
    const float* Wu1h = W1h + w * HID;

    unsigned int phase = 0;

    for (int t = 0; t < T_STEPS; t++) {
        const int p = t & 1;

        // masks: smem copy (for staging) + registers (for cell update)
        msm[tid] = 1.0f - (float)done[t * BATCH + tid];
        float mk[4];
#pragma unroll
        for (int i = 0; i < 4; i++) mk[i] = 1.0f - (float)done[t * BATCH + lane + (i << 5)];

        // prefetch pre0 (hidden under layer-0 accum)
        float pre[16];
        const float* pbase = g_pre0 + ((size_t)t * G4H + u) * BATCH;
#pragma unroll
        for (int g = 0; g < 4; g++)
#pragma unroll
            for (int i = 0; i < 4; i++)
                pre[(g << 2) + i] = __ldcg(&pbase[((size_t)g << 9) * BATCH + (i << 5) + lane]);

        // ---- layer 0 ----
        unsigned long long acc2[16];
#pragma unroll
        for (int i = 0; i < 16; i++) acc2[i] = 0ull;
        accum_K<true>(acc2, &g_h0[p][0][0], Wu0, msm, hbuf, tid);

#pragma unroll
        for (int i = 0; i < 4; i++) {
            float2 vi = unpk(acc2[ 0 + i]);
            float2 vf = unpk(acc2[ 4 + i]);
            float2 vg = unpk(acc2[ 8 + i]);
            float2 vo = unpk(acc2[12 + i]);
            float ig = sigmoidf_(vi.x + vi.y + pre[ 0 + i]);
            float fg = sigmoidf_(vf.x + vf.y + pre[ 4 + i]);
            float gg = tanhf    (vg.x + vg.y + pre[ 8 + i]);
            float og = sigmoidf_(vo.x + vo.y + pre[12 + i]);
            float c  = fmaf(fg, c0r[i] * mk[i], ig * gg);
            c0r[i]   = c;
            g_h0[p ^ 1][lane + (i << 5)][u] = og * tanhf(c);
        }

        grid_bar(++phase);

        // ---- layer 1 ----
#pragma unroll
        for (int i = 0; i < 16; i++) acc2[i] = 0ull;
        accum_K<false>(acc2, &g_h0[p ^ 1][0][0], Wu1i, msm, hbuf, tid);
        accum_K<true >(acc2, &g_h1[p][0][0],     Wu1h, msm, hbuf, tid);

#pragma unroll
        for (int i = 0; i < 4; i++) {
            int b = lane + (i << 5);
            float2 vi = unpk(acc2[ 0 + i]);
            float2 vf = unpk(acc2[ 4 + i]);
            float2 vg = unpk(acc2[ 8 + i]);
            float2 vo = unpk(acc2[12 + i]);
            float ig = sigmoidf_(vi.x + vi.y + bias1[0]);
            float fg = sigmoidf_(vf.x + vf.y + bias1[1]);
            float gg = tanhf    (vg.x + vg.y + bias1[2]);
            float og = sigmoidf_(vo.x + vo.y + bias1[3]);
            float c  = fmaf(fg, c1r[i] * mk[i], ig * gg);
            c1r[i]   = c;
            float h  = og * tanhf(c);
            g_h1[p ^ 1][b][u] = h;
            g_hidden[((size_t)t * BATCH + b) * HID + u] = h;
        }
    }

    grid_bar(++phase);   // all blocks' final-step writes visible before copy-out

#pragma unroll
    for (int i = 0; i < 4; i++) {
        int b = lane + (i << 5);
        out_cT[(0 * BATCH + b) * HID + u] = c0r[i];
        out_cT[(1 * BATCH + b) * HID + u] = c1r[i];
    }
    for (int i = bid * NTHR + tid; i < BATCH * HID; i += NBLK * NTHR) {
        out_hT[i]               = __ldcg(&(&g_h0[0][0][0])[i]);
        out_hT[BATCH * HID + i] = __ldcg(&(&g_h1[0][0][0])[i]);
    }
}

// ---------------- actor/critic heads -----------------------------------------
__global__ void __launch_bounds__(256)
head_kernel(const float* __restrict__ Wa, const float* __restrict__ ba,
            const float* __restrict__ Wc, const float* __restrict__ bc,
            float* __restrict__ out)
{
    __shared__ float Ws[NACT * HID];
    __shared__ float bs[NACT];
    for (int i = threadIdx.x; i < 18 * HID; i += blockDim.x) Ws[i] = Wa[i];
    for (int i = threadIdx.x; i < HID; i += blockDim.x) Ws[18 * HID + i] = Wc[i];
    if (threadIdx.x < 18) bs[threadIdx.x] = ba[threadIdx.x];
    if (threadIdx.x == 18) bs[18] = bc[0];
    __syncthreads();

    const int warp = threadIdx.x >> 5;
    const int lane = threadIdx.x & 31;
    const size_t m = (size_t)blockIdx.x * 8 + warp;

    const float* hrow = &g_hidden[m * HID];
    float hv[16];
#pragma unroll
    for (int j = 0; j < 16; j++) hv[j] = hrow[lane + j * 32];

#pragma unroll
    for (int a = 0; a < NACT; a++) {
        float s = 0.f;
#pragma unroll
        for (int j = 0; j < 16; j++) s = fmaf(hv[j], Ws[a * HID + lane + j * 32], s);
#pragma unroll
        for (int off = 16; off > 0; off >>= 1) s += __shfl_xor_sync(0xffffffffu, s, off);
        if (lane == a) out[m * NACT + a] = s + bs[a];
    }
}

// ---------------- launch ------------------------------------------------------
extern "C" void kernel_launch(void* const* d_in, const int* in_sizes, int n_in,
                              void* d_out, int out_size)
{
    (void)in_sizes; (void)n_in; (void)out_size;
    const float* x     = (const float*)d_in[0];
    const int*   done  = (const int*)  d_in[1];
    const float* h0    = (const float*)d_in[2];
    const float* c0    = (const float*)d_in[3];
    const float* W_ih0 = (const float*)d_in[4];
    const float* W_hh0 = (const float*)d_in[5];
    const float* b_ih0 = (const float*)d_in[6];
    const float* b_hh0 = (const float*)d_in[7];
    const float* W_ih1 = (const float*)d_in[8];
    const float* W_hh1 = (const float*)d_in[9];
    const float* b_ih1 = (const float*)d_in[10];
    const float* b_hh1 = (const float*)d_in[11];
    const float* W_a   = (const float*)d_in[12];
    const float* b_a   = (const float*)d_in[13];
    const float* W_c   = (const float*)d_in[14];
    const float* b_c   = (const float*)d_in[15];

    float* out    = (float*)d_out;
    float* out_hT = out + (size_t)T_STEPS * BATCH * NACT;
    float* out_cT = out_hT + 2 * BATCH * HID;

    const int smem_bytes = (3 * 16 * HID + 128 * 132 + 128) * (int)sizeof(float); // 166,400 B
    cudaFuncSetAttribute(lstm_kernel, cudaFuncAttributeMaxDynamicSharedMemorySize, smem_bytes);

    init_kernel<<<64, 256>>>(h0);

    dim3 gg(G4H / 64, (T_STEPS * BATCH) / 64);
    pre_gemm_kernel<<<gg, 256>>>(x, W_ih0, b_ih0, b_hh0);

    lstm_kernel<<<NBLK, NTHR, smem_bytes>>>(done, c0, W_hh0, W_ih1, W_hh1,
                                            b_ih1, b_hh1, out_hT, out_cT);

    head_kernel<<<(T_STEPS * BATCH) / 8, 256>>>(W_a, b_a, W_c, b_c, out);
}